// round 5
// baseline (speedup 1.0000x reference)
#include <cuda_runtime.h>
#include <math.h>

#define CB 2
#define CL 12
#define CN 1024
#define CD 768
#define CH 12
#define CM 3072
#define CNL 2
#define CR 2048            /* B*N rows per dir */
#define CKQ 1536           /* 2*D concat K */
#define CN3 2304           /* 3*D */
#define XTOT 18874368      /* B*L*N*D */
#define RD (CR*CD)

// ---------------- static device scratch (no allocs allowed) ----------------
__device__ float g_pos[XTOT];
__device__ float g_xin[XTOT];
__device__ float g_Wcat[2*CNL*CKQ*CN3];
__device__ float g_bcatv[2*CNL*CN3];
__device__ float g_h[2*RD];
__device__ float g_hin[2*RD];
__device__ float g_Abuf[2*CR*CKQ];
__device__ float g_qkv[2*CR*CN3];
__device__ float g_kvbuf[2*CB*CH*4096];
__device__ float g_obuf[2*RD];
__device__ float g_x2[2*RD];
__device__ float g_xn2[2*RD];
__device__ float g_t1[2*CR*CM];

// ---------------- elementwise setup ----------------
__global__ void k_pos(const float* __restrict__ tpos, const float* __restrict__ spos){
    int i = blockIdx.x*256 + threadIdx.x;
    if (i >= XTOT) return;
    int d = i % CD;
    int r = i / CD;
    int n = r % CN;
    int bl = r / CN;
    int l = bl % CL;
    int b = bl / CL;
    g_pos[i] = tpos[(b*CL + l)*CD + d] * spos[(b*CN + n)*CD + d];
}

__global__ void k_stack(const float* __restrict__ Wqkv, const float* __restrict__ Wqkvh){
    int i = blockIdx.x*256 + threadIdx.x;
    const int TOT = 2*CNL*CKQ*CN3;
    if (i >= TOT) return;
    int n = i % CN3;
    int t = i / CN3;
    int k = t % CKQ;
    int dl = t / CKQ;   // dir*CNL + lay
    float v;
    if (k < CD) v = Wqkv [((long)dl*CD + k     )*CN3 + n];
    else        v = Wqkvh[((long)dl*CD + (k-CD))*CN3 + n];
    g_Wcat[i] = v;
}

__global__ void k_bcat(const float* __restrict__ bqkv, const float* __restrict__ bqkvh){
    int i = blockIdx.x*256 + threadIdx.x;
    if (i >= 2*CNL*CN3) return;
    g_bcatv[i] = bqkv[i] + bqkvh[i];
}

__global__ void k_addpos(const float* __restrict__ src){
    int i = blockIdx.x*256 + threadIdx.x;
    if (i >= XTOT) return;
    g_xin[i] = src[i] + g_pos[i];
}

__global__ void k_copyh(const float* __restrict__ hidden){
    int i = blockIdx.x*256 + threadIdx.x;
    if (i >= 2*RD) return;
    g_h[i] = hidden[i % RD];
}

// ---------------- LN helpers ----------------
__device__ __forceinline__ float blk_reduce(float v, float* red){
    int tid = threadIdx.x;
    red[tid] = v; __syncthreads();
    #pragma unroll
    for (int s = 128; s > 0; s >>= 1){
        if (tid < s) red[tid] += red[tid + s];
        __syncthreads();
    }
    float r = red[0]; __syncthreads();
    return r;
}

// Per (dir,row): hin = h + pos[sel]; A[0:768]=LN(x_t), A[768:1536]=LN(hin)
__global__ void k_buildA(int t, int lay,
        const float* __restrict__ lni_g, const float* __restrict__ lni_b,
        const float* __restrict__ lnh_g, const float* __restrict__ lnh_b){
    __shared__ float sx[CD], sh[CD], red[256];
    int r = blockIdx.x, dir = blockIdx.y;
    int b = r >> 10, n = r & 1023;
    int tsel   = (dir == 0) ? t   : (CL-1-t);
    int posidx = (dir == 0) ? lay : tsel;
    const float* xrow = g_xin + ((long)(b*CL + tsel)*CN + n)*CD;
    const float* hrow = g_h   + (long)dir*RD + (long)r*CD;
    const float* prow = g_pos + ((long)(b*CL + posidx)*CN + n)*CD;
    float* hinrow = g_hin  + (long)dir*RD + (long)r*CD;
    float* Arow   = g_Abuf + ((long)dir*CR + r)*CKQ;
    int tid = threadIdx.x;
    float lsx = 0.f, lsh = 0.f;
    for (int i = tid; i < CD; i += 256){
        float xv = xrow[i]; sx[i] = xv; lsx += xv;
        float hv = hrow[i] + prow[i]; sh[i] = hv; hinrow[i] = hv; lsh += hv;
    }
    __syncthreads();
    float mx = blk_reduce(lsx, red) * (1.f/CD);
    float mh = blk_reduce(lsh, red) * (1.f/CD);
    float vx = 0.f, vh = 0.f;
    for (int i = tid; i < CD; i += 256){
        float dx = sx[i]-mx; vx += dx*dx;
        float dh = sh[i]-mh; vh += dh*dh;
    }
    float varx = blk_reduce(vx, red) * (1.f/CD);
    float varh = blk_reduce(vh, red) * (1.f/CD);
    float rsx = rsqrtf(varx + 1e-5f);
    float rsh = rsqrtf(varh + 1e-5f);
    int po = (dir*CNL + lay)*CD;
    for (int i = tid; i < CD; i += 256){
        Arow[i]      = (sx[i]-mx)*rsx*lni_g[po+i] + lni_b[po+i];
        Arow[CD + i] = (sh[i]-mh)*rsh*lnh_g[po+i] + lnh_b[po+i];
    }
}

__global__ void k_ln2(int lay, const float* __restrict__ lno_g, const float* __restrict__ lno_b){
    __shared__ float sx[CD], red[256];
    int r = blockIdx.x, dir = blockIdx.y;
    const float* src = g_x2  + (long)dir*RD + (long)r*CD;
    float*       dst = g_xn2 + (long)dir*RD + (long)r*CD;
    int tid = threadIdx.x;
    float ls = 0.f;
    for (int i=tid;i<CD;i+=256){ float v = src[i]; sx[i]=v; ls+=v; }
    __syncthreads();
    float m = blk_reduce(ls, red)*(1.f/CD);
    float lv=0.f;
    for (int i=tid;i<CD;i+=256){ float d=sx[i]-m; lv+=d*d; }
    float var = blk_reduce(lv, red)*(1.f/CD);
    float rs = rsqrtf(var+1e-5f);
    int po = (dir*CNL+lay)*CD;
    for (int i=tid;i<CD;i+=256) dst[i] = (sx[i]-m)*rs*lno_g[po+i] + lno_b[po+i];
}

// ---------------- linear attention (tiny batched GEMMs) ----------------
// kv[d,e] = sum_j k[j,d] * v[j,e]  per (dir,b,h)
__global__ void k_kv(){
    int h = blockIdx.x, b = blockIdx.y, dir = blockIdx.z;
    __shared__ float ks[64][65], vs[64][65];
    const float* qkv = g_qkv + (long)dir*CR*CN3;
    int tid = threadIdx.x;
    int ty = tid >> 4, tx = tid & 15;
    float acc[4][4] = {};
    for (int j0 = 0; j0 < CN; j0 += 64){
        for (int l = tid; l < 64*16; l += 256){
            int rr = l >> 4, cc = (l & 15) << 2;
            const float* base = qkv + ((long)(b*CN + j0 + rr))*CN3 + h*64 + cc;
            float4 k4 = *(const float4*)(base + CD);
            float4 v4 = *(const float4*)(base + 2*CD);
            ks[rr][cc]=k4.x; ks[rr][cc+1]=k4.y; ks[rr][cc+2]=k4.z; ks[rr][cc+3]=k4.w;
            vs[rr][cc]=v4.x; vs[rr][cc+1]=v4.y; vs[rr][cc+2]=v4.z; vs[rr][cc+3]=v4.w;
        }
        __syncthreads();
        #pragma unroll 8
        for (int j = 0; j < 64; j++){
            float kk[4], vv[4];
            #pragma unroll
            for (int i=0;i<4;i++){ kk[i]=ks[j][ty*4+i]; vv[i]=vs[j][tx*4+i]; }
            #pragma unroll
            for (int i=0;i<4;i++)
                #pragma unroll
                for (int e=0;e<4;e++) acc[i][e] += kk[i]*vv[e];
        }
        __syncthreads();
    }
    float* outp = g_kvbuf + (((long)dir*CB + b)*CH + h)*4096;
    #pragma unroll
    for (int i=0;i<4;i++)
        #pragma unroll
        for (int e=0;e<4;e++)
            outp[(ty*4+i)*64 + tx*4+e] = acc[i][e];
}

// o[i, h*64+e] = sum_d q[i,d] * kv[d,e]
__global__ void k_o(){
    int it = blockIdx.x;             // 64-row tile
    int bh = blockIdx.y;
    int dir = blockIdx.z;
    int b = bh / CH, h = bh % CH;
    __shared__ float kvs[64][65], qs[64][65];
    const float* kvp = g_kvbuf + (((long)dir*CB + b)*CH + h)*4096;
    int tid = threadIdx.x;
    for (int l = tid; l < 4096; l += 256) kvs[l>>6][l&63] = kvp[l];
    const float* qbase = g_qkv + (long)dir*CR*CN3 + ((long)(b*CN + it*64))*CN3 + h*64;
    for (int l = tid; l < 64*16; l += 256){
        int rr = l >> 4, cc = (l & 15) << 2;
        float4 q4 = *(const float4*)(qbase + (long)rr*CN3 + cc);
        qs[rr][cc]=q4.x; qs[rr][cc+1]=q4.y; qs[rr][cc+2]=q4.z; qs[rr][cc+3]=q4.w;
    }
    __syncthreads();
    int ty = tid >> 4, tx = tid & 15;
    float acc[4][4] = {};
    #pragma unroll 8
    for (int d = 0; d < 64; d++){
        float qv[4], kvv[4];
        #pragma unroll
        for (int i=0;i<4;i++){ qv[i]=qs[ty*4+i][d]; kvv[i]=kvs[d][tx*4+i]; }
        #pragma unroll
        for (int i=0;i<4;i++)
            #pragma unroll
            for (int e=0;e<4;e++) acc[i][e] += qv[i]*kvv[e];
    }
    float* orow = g_obuf + (long)dir*RD + ((long)(b*CN + it*64))*CD + h*64;
    #pragma unroll
    for (int i=0;i<4;i++)
        #pragma unroll
        for (int e=0;e<4;e++)
            orow[(long)(ty*4+i)*CD + tx*4+e] = acc[i][e];
}

// ---------------- fp32 tiled GEMM, batched over dir (blockIdx.z), fused epilogues ----------------
// EPI 1: qkv  -> elu(x)+1 on q,k columns (col<1536)
// EPI 2: attn -> C=x2=attn+x_t ; aux2(h carry)=attn+hin
// EPI 3: gelu (exact, via normcdf)
// EPI 4: y    -> yacc[time] += y + x2  (scatter into layer output accumulator)
template<int EPI>
__global__ __launch_bounds__(256) void k_gemm(
    const float* __restrict__ Ab, long Ads, int lda,
    const float* __restrict__ Wb, long Wds, int ldw,
    const float* __restrict__ biasb, int bds,
    float* __restrict__ Cb, long Cds, int ldc,
    int K,
    const float* __restrict__ aux1, float* __restrict__ aux2,
    const float* __restrict__ aux3, float* __restrict__ aux4,
    int tsel0, int tsel1)
{
    int dir = blockIdx.z;
    const float* A = Ab + dir*Ads;
    const float* W = Wb + dir*Wds;
    const float* bias = biasb + dir*bds;
    float* C = Cb + dir*Cds;
    int bm = blockIdx.y, bn = blockIdx.x;
    __shared__ float As[8][128];
    __shared__ float Bs[8][128];
    int tid = threadIdx.x;
    int tm = (tid >> 4) << 3, tn = (tid & 15) << 3;
    int arow = tid >> 1, acol = (tid & 1) << 2;
    int brow = tid >> 5, bcol = (tid & 31) << 2;
    const float* Aptr = A + (long)(bm*128 + arow)*lda + acol;
    const float* Wptr = W + (long)brow*ldw + bn*128 + bcol;
    float acc[8][8] = {};
    float4 av = *(const float4*)(Aptr);
    float4 wv = *(const float4*)(Wptr);
    for (int k0 = 0; k0 < K; k0 += 8){
        As[acol+0][arow]=av.x; As[acol+1][arow]=av.y; As[acol+2][arow]=av.z; As[acol+3][arow]=av.w;
        *(float4*)&Bs[brow][bcol] = wv;
        __syncthreads();
        if (k0 + 8 < K){
            av = *(const float4*)(Aptr + k0 + 8);
            wv = *(const float4*)(Wptr + (long)(k0+8)*ldw);
        }
        #pragma unroll
        for (int k = 0; k < 8; k++){
            float4 a0 = *(const float4*)&As[k][tm];
            float4 a1 = *(const float4*)&As[k][tm+4];
            float4 b0 = *(const float4*)&Bs[k][tn];
            float4 b1 = *(const float4*)&Bs[k][tn+4];
            float ra[8] = {a0.x,a0.y,a0.z,a0.w,a1.x,a1.y,a1.z,a1.w};
            float rb[8] = {b0.x,b0.y,b0.z,b0.w,b1.x,b1.y,b1.z,b1.w};
            #pragma unroll
            for (int i=0;i<8;i++)
                #pragma unroll
                for (int j=0;j<8;j++) acc[i][j] += ra[i]*rb[j];
        }
        __syncthreads();
    }
    int row0 = bm*128 + tm, col0 = bn*128 + tn;
    #pragma unroll
    for (int i=0;i<8;i++){
        int row = row0 + i;
        #pragma unroll
        for (int j=0;j<8;j++){
            int col = col0 + j;
            float v = acc[i][j] + bias[col];
            long ro = (long)row*ldc + col;
            if (EPI == 1){
                if (col < CKQ) v = (v > 0.f) ? v + 1.f : expf(v);
                C[ro] = v;
            } else if (EPI == 2){
                float hv = aux1[(long)dir*RD + ro];
                aux2[(long)dir*RD + ro] = v + hv;              // new h carry
                int bb = row >> 10, nn = row & 1023;
                int ts = dir ? tsel1 : tsel0;
                float xv = aux3[((long)(bb*CL + ts)*CN + nn)*CD + col];
                C[ro] = v + xv;                                 // x2
            } else if (EPI == 3){
                C[ro] = v * normcdff(v);
            } else if (EPI == 4){
                float x2v = aux1[(long)dir*RD + ro];
                float val = v + x2v;
                int bb = row >> 10, nn = row & 1023;
                int ts = dir ? tsel1 : tsel0;
                long xo = ((long)(bb*CL + ts)*CN + nn)*CD + col;
                aux4[xo] += val;
            } else {
                C[ro] = v;
            }
        }
    }
}

// ---------------- host ----------------
extern "C" void kernel_launch(void* const* d_in, const int* in_sizes, int n_in,
                              void* d_out, int out_size){
    (void)in_sizes; (void)n_in; (void)out_size;
    const float* x      = (const float*)d_in[0];
    const float* hidden = (const float*)d_in[1];
    const float* spos   = (const float*)d_in[2];
    const float* tpos   = (const float*)d_in[3];
    const float* lni_g  = (const float*)d_in[4];
    const float* lni_b  = (const float*)d_in[5];
    const float* lnh_g  = (const float*)d_in[6];
    const float* lnh_b  = (const float*)d_in[7];
    const float* lno_g  = (const float*)d_in[8];
    const float* lno_b  = (const float*)d_in[9];
    const float* Wqkv   = (const float*)d_in[10];
    const float* bqkv   = (const float*)d_in[11];
    const float* Wqkvh  = (const float*)d_in[12];
    const float* bqkvh  = (const float*)d_in[13];
    const float* Wout   = (const float*)d_in[14];
    const float* bout   = (const float*)d_in[15];
    const float* W1     = (const float*)d_in[16];
    const float* b1     = (const float*)d_in[17];
    const float* W2     = (const float*)d_in[18];
    const float* b2     = (const float*)d_in[19];
    float* out = (float*)d_out;

    float *pWcat, *pbcat, *pA, *pqkv, *po, *px2, *pxn2, *pt1, *phin, *ph, *pxin;
    cudaGetSymbolAddress((void**)&pWcat, g_Wcat);
    cudaGetSymbolAddress((void**)&pbcat, g_bcatv);
    cudaGetSymbolAddress((void**)&pA,    g_Abuf);
    cudaGetSymbolAddress((void**)&pqkv,  g_qkv);
    cudaGetSymbolAddress((void**)&po,    g_obuf);
    cudaGetSymbolAddress((void**)&px2,   g_x2);
    cudaGetSymbolAddress((void**)&pxn2,  g_xn2);
    cudaGetSymbolAddress((void**)&pt1,   g_t1);
    cudaGetSymbolAddress((void**)&phin,  g_hin);
    cudaGetSymbolAddress((void**)&ph,    g_h);
    cudaGetSymbolAddress((void**)&pxin,  g_xin);

    const int eb = 256;
    k_pos  <<<(XTOT+eb-1)/eb, eb>>>(tpos, spos);
    k_stack<<<(2*CNL*CKQ*CN3+eb-1)/eb, eb>>>(Wqkv, Wqkvh);
    k_bcat <<<(2*CNL*CN3+eb-1)/eb, eb>>>(bqkv, bqkvh);

    for (int lay = 0; lay < CNL; lay++){
        // Layer 0 accumulates into d_out (used as scratch), layer 1 reads it
        // via k_addpos (snapshot into g_xin) then re-zeroes d_out and
        // accumulates the final result. Stream-ordered; capture-legal.
        const float* xsrc = (lay == 0) ? x : out;
        float* yacc       = out;
        k_addpos<<<(XTOT+eb-1)/eb, eb>>>(xsrc);
        cudaMemsetAsync(yacc, 0, (size_t)XTOT*sizeof(float));
        k_copyh<<<(2*RD+eb-1)/eb, eb>>>(hidden);
        for (int t = 0; t < CL; t++){
            int ts0 = t, ts1 = CL-1-t;
            k_buildA<<<dim3(CR,2), 256>>>(t, lay, lni_g, lni_b, lnh_g, lnh_b);
            // QKV: [xn|hn](2048x1536) @ Wcat(1536x2304) + bcat, elu+1 on q,k
            k_gemm<1><<<dim3(CN3/128, CR/128, 2), 256>>>(
                pA, (long)CR*CKQ, CKQ,
                pWcat + (long)lay*CKQ*CN3, (long)CNL*CKQ*CN3, CN3,
                pbcat + lay*CN3, CNL*CN3,
                pqkv, (long)CR*CN3, CN3,
                CKQ,
                nullptr, nullptr, nullptr, nullptr, ts0, ts1);
            k_kv<<<dim3(CH, CB, 2), 256>>>();
            k_o <<<dim3(CN/64, CB*CH, 2), 256>>>();
            // attn proj: o(2048x768) @ Wout + bout; x2 = attn+x_t ; h = attn+hin
            k_gemm<2><<<dim3(CD/128, CR/128, 2), 256>>>(
                po, (long)RD, CD,
                Wout + (long)lay*CD*CD, (long)CNL*CD*CD, CD,
                bout + lay*CD, CNL*CD,
                px2, (long)RD, CD,
                CD,
                phin, ph, pxin, nullptr, ts0, ts1);
            k_ln2<<<dim3(CR,2), 256>>>(lay, lno_g, lno_b);
            // MLP up: xn2(2048x768) @ W1 + b1, gelu
            k_gemm<3><<<dim3(CM/128, CR/128, 2), 256>>>(
                pxn2, (long)RD, CD,
                W1 + (long)lay*CD*CM, (long)CNL*CD*CM, CM,
                b1 + lay*CM, CNL*CM,
                pt1, (long)CR*CM, CM,
                CD,
                nullptr, nullptr, nullptr, nullptr, ts0, ts1);
            // MLP down: t1(2048x3072) @ W2 + b2; yacc[time] += x2 + y
            k_gemm<4><<<dim3(CD/128, CR/128, 2), 256>>>(
                pt1, (long)CR*CM, CM,
                W2 + (long)lay*CM*CD, (long)CNL*CM*CD, CD,
                b2 + lay*CD, CNL*CD,
                px2 /*unused C*/, (long)RD, CD,
                CM,
                px2, nullptr, nullptr, yacc, ts0, ts1);
        }
    }
}

// round 7
// speedup vs baseline: 2.2917x; 2.2917x over previous
#include <cuda_runtime.h>
#include <math.h>

#define CB 2
#define CL 12
#define CN 1024
#define CD 768
#define CH 12
#define CM 3072
#define CNL 2
#define CR 2048            /* B*N rows per dir */
#define CKQ 1536           /* 2*D concat K */
#define CN3 2304           /* 3*D */
#define XTOT 18874368      /* B*L*N*D */
#define RD (CR*CD)

// ---------------- static device scratch (no allocs allowed) ----------------
__device__ float g_pos[XTOT];
__device__ float g_xin[XTOT];
__device__ float g_Wcat[2*CNL*CKQ*CN3];
__device__ float g_bcatv[2*CNL*CN3];
__device__ float g_h[2*RD];
__device__ float g_hin[2*RD];
__device__ float g_Abuf[2*CR*CKQ];
__device__ float g_qkv[2*CR*CN3];
__device__ float g_kvbuf[2*CB*CH*4096];
__device__ float g_obuf[2*RD];
__device__ float g_x2[2*RD];
__device__ float g_xn2[2*RD];
__device__ float g_t1[2*CR*CM];

// ---------------- elementwise setup ----------------
__global__ void k_pos(const float* __restrict__ tpos, const float* __restrict__ spos){
    int i = blockIdx.x*256 + threadIdx.x;
    if (i >= XTOT) return;
    int d = i % CD;
    int r = i / CD;
    int n = r % CN;
    int bl = r / CN;
    int l = bl % CL;
    int b = bl / CL;
    g_pos[i] = tpos[(b*CL + l)*CD + d] * spos[(b*CN + n)*CD + d];
}

__global__ void k_stack(const float* __restrict__ Wqkv, const float* __restrict__ Wqkvh){
    int i = blockIdx.x*256 + threadIdx.x;
    const int TOT = 2*CNL*CKQ*CN3;
    if (i >= TOT) return;
    int n = i % CN3;
    int t = i / CN3;
    int k = t % CKQ;
    int dl = t / CKQ;   // dir*CNL + lay
    float v;
    if (k < CD) v = Wqkv [((long)dl*CD + k     )*CN3 + n];
    else        v = Wqkvh[((long)dl*CD + (k-CD))*CN3 + n];
    g_Wcat[i] = v;
}

__global__ void k_bcat(const float* __restrict__ bqkv, const float* __restrict__ bqkvh){
    int i = blockIdx.x*256 + threadIdx.x;
    if (i >= 2*CNL*CN3) return;
    g_bcatv[i] = bqkv[i] + bqkvh[i];
}

__global__ void k_addpos(const float* __restrict__ src){
    int i = blockIdx.x*256 + threadIdx.x;
    if (i >= XTOT) return;
    g_xin[i] = src[i] + g_pos[i];
}

__global__ void k_copyh(const float* __restrict__ hidden){
    int i = blockIdx.x*256 + threadIdx.x;
    if (i >= 2*RD) return;
    g_h[i] = hidden[i % RD];
}

// ---------------- LN helpers ----------------
__device__ __forceinline__ float blk_reduce(float v, float* red){
    int tid = threadIdx.x;
    red[tid] = v; __syncthreads();
    #pragma unroll
    for (int s = 128; s > 0; s >>= 1){
        if (tid < s) red[tid] += red[tid + s];
        __syncthreads();
    }
    float r = red[0]; __syncthreads();
    return r;
}

// Per (dir,row): hin = h + pos[sel]; A[0:768]=LN(x_t), A[768:1536]=LN(hin)
__global__ void k_buildA(int t, int lay,
        const float* __restrict__ lni_g, const float* __restrict__ lni_b,
        const float* __restrict__ lnh_g, const float* __restrict__ lnh_b){
    __shared__ float sx[CD], sh[CD], red[256];
    int r = blockIdx.x, dir = blockIdx.y;
    int b = r >> 10, n = r & 1023;
    int tsel   = (dir == 0) ? t   : (CL-1-t);
    int posidx = (dir == 0) ? lay : tsel;
    const float* xrow = g_xin + ((long)(b*CL + tsel)*CN + n)*CD;
    const float* hrow = g_h   + (long)dir*RD + (long)r*CD;
    const float* prow = g_pos + ((long)(b*CL + posidx)*CN + n)*CD;
    float* hinrow = g_hin  + (long)dir*RD + (long)r*CD;
    float* Arow   = g_Abuf + ((long)dir*CR + r)*CKQ;
    int tid = threadIdx.x;
    float lsx = 0.f, lsh = 0.f;
    for (int i = tid; i < CD; i += 256){
        float xv = xrow[i]; sx[i] = xv; lsx += xv;
        float hv = hrow[i] + prow[i]; sh[i] = hv; hinrow[i] = hv; lsh += hv;
    }
    __syncthreads();
    float mx = blk_reduce(lsx, red) * (1.f/CD);
    float mh = blk_reduce(lsh, red) * (1.f/CD);
    float vx = 0.f, vh = 0.f;
    for (int i = tid; i < CD; i += 256){
        float dx = sx[i]-mx; vx += dx*dx;
        float dh = sh[i]-mh; vh += dh*dh;
    }
    float varx = blk_reduce(vx, red) * (1.f/CD);
    float varh = blk_reduce(vh, red) * (1.f/CD);
    float rsx = rsqrtf(varx + 1e-5f);
    float rsh = rsqrtf(varh + 1e-5f);
    int po = (dir*CNL + lay)*CD;
    for (int i = tid; i < CD; i += 256){
        Arow[i]      = (sx[i]-mx)*rsx*lni_g[po+i] + lni_b[po+i];
        Arow[CD + i] = (sh[i]-mh)*rsh*lnh_g[po+i] + lnh_b[po+i];
    }
}

__global__ void k_ln2(int lay, const float* __restrict__ lno_g, const float* __restrict__ lno_b){
    __shared__ float sx[CD], red[256];
    int r = blockIdx.x, dir = blockIdx.y;
    const float* src = g_x2  + (long)dir*RD + (long)r*CD;
    float*       dst = g_xn2 + (long)dir*RD + (long)r*CD;
    int tid = threadIdx.x;
    float ls = 0.f;
    for (int i=tid;i<CD;i+=256){ float v = src[i]; sx[i]=v; ls+=v; }
    __syncthreads();
    float m = blk_reduce(ls, red)*(1.f/CD);
    float lv=0.f;
    for (int i=tid;i<CD;i+=256){ float d=sx[i]-m; lv+=d*d; }
    float var = blk_reduce(lv, red)*(1.f/CD);
    float rs = rsqrtf(var+1e-5f);
    int po = (dir*CNL+lay)*CD;
    for (int i=tid;i<CD;i+=256) dst[i] = (sx[i]-m)*rs*lno_g[po+i] + lno_b[po+i];
}

// ---------------- linear attention (tiny batched GEMMs) ----------------
__global__ void k_kv(){
    int h = blockIdx.x, b = blockIdx.y, dir = blockIdx.z;
    __shared__ float ks[64][65], vs[64][65];
    const float* qkv = g_qkv + (long)dir*CR*CN3;
    int tid = threadIdx.x;
    int ty = tid >> 4, tx = tid & 15;
    float acc[4][4] = {};
    for (int j0 = 0; j0 < CN; j0 += 64){
        for (int l = tid; l < 64*16; l += 256){
            int rr = l >> 4, cc = (l & 15) << 2;
            const float* base = qkv + ((long)(b*CN + j0 + rr))*CN3 + h*64 + cc;
            float4 k4 = *(const float4*)(base + CD);
            float4 v4 = *(const float4*)(base + 2*CD);
            ks[rr][cc]=k4.x; ks[rr][cc+1]=k4.y; ks[rr][cc+2]=k4.z; ks[rr][cc+3]=k4.w;
            vs[rr][cc]=v4.x; vs[rr][cc+1]=v4.y; vs[rr][cc+2]=v4.z; vs[rr][cc+3]=v4.w;
        }
        __syncthreads();
        #pragma unroll 8
        for (int j = 0; j < 64; j++){
            float kk[4], vv[4];
            #pragma unroll
            for (int i=0;i<4;i++){ kk[i]=ks[j][ty*4+i]; vv[i]=vs[j][tx*4+i]; }
            #pragma unroll
            for (int i=0;i<4;i++)
                #pragma unroll
                for (int e=0;e<4;e++) acc[i][e] += kk[i]*vv[e];
        }
        __syncthreads();
    }
    float* outp = g_kvbuf + (((long)dir*CB + b)*CH + h)*4096;
    #pragma unroll
    for (int i=0;i<4;i++)
        #pragma unroll
        for (int e=0;e<4;e++)
            outp[(ty*4+i)*64 + tx*4+e] = acc[i][e];
}

__global__ void k_o(){
    int it = blockIdx.x;             // 64-row tile
    int bh = blockIdx.y;
    int dir = blockIdx.z;
    int b = bh / CH, h = bh % CH;
    __shared__ float kvs[64][65], qs[64][65];
    const float* kvp = g_kvbuf + (((long)dir*CB + b)*CH + h)*4096;
    int tid = threadIdx.x;
    for (int l = tid; l < 4096; l += 256) kvs[l>>6][l&63] = kvp[l];
    const float* qbase = g_qkv + (long)dir*CR*CN3 + ((long)(b*CN + it*64))*CN3 + h*64;
    for (int l = tid; l < 64*16; l += 256){
        int rr = l >> 4, cc = (l & 15) << 2;
        float4 q4 = *(const float4*)(qbase + (long)rr*CN3 + cc);
        qs[rr][cc]=q4.x; qs[rr][cc+1]=q4.y; qs[rr][cc+2]=q4.z; qs[rr][cc+3]=q4.w;
    }
    __syncthreads();
    int ty = tid >> 4, tx = tid & 15;
    float acc[4][4] = {};
    #pragma unroll 8
    for (int d = 0; d < 64; d++){
        float qv[4], kvv[4];
        #pragma unroll
        for (int i=0;i<4;i++){ qv[i]=qs[ty*4+i][d]; kvv[i]=kvs[d][tx*4+i]; }
        #pragma unroll
        for (int i=0;i<4;i++)
            #pragma unroll
            for (int e=0;e<4;e++) acc[i][e] += qv[i]*kvv[e];
    }
    float* orow = g_obuf + (long)dir*RD + ((long)(b*CN + it*64))*CD + h*64;
    #pragma unroll
    for (int i=0;i<4;i++)
        #pragma unroll
        for (int e=0;e<4;e++)
            orow[(long)(ty*4+i)*CD + tx*4+e] = acc[i][e];
}

// ---------------- tf32 tensor-core GEMM (mma.sync m16n8k8), fused epilogues ----------------
__device__ __forceinline__ unsigned f2tf(float f){
    unsigned u; asm("cvt.rna.tf32.f32 %0, %1;" : "=r"(u) : "f"(f)); return u;
}
__device__ __forceinline__ void mma_tf32(float& c0, float& c1, float& c2, float& c3,
        unsigned a0, unsigned a1, unsigned a2, unsigned a3, unsigned b0, unsigned b1){
    asm volatile("mma.sync.aligned.m16n8k8.row.col.f32.tf32.tf32.f32 "
        "{%0,%1,%2,%3}, {%4,%5,%6,%7}, {%8,%9}, {%0,%1,%2,%3};\n"
        : "+f"(c0), "+f"(c1), "+f"(c2), "+f"(c3)
        : "r"(a0), "r"(a1), "r"(a2), "r"(a3), "r"(b0), "r"(b1));
}

// EPI 1: qkv  -> elu(x)+1 on q,k columns (col<1536)
// EPI 2: attn -> C=x2=attn+x_t ; aux2(h carry)=attn+hin
// EPI 3: gelu (exact, via normcdf)
// EPI 4: y    -> yacc[time] += y + x2  (scatter into layer output accumulator)
template<int EPI>
__global__ __launch_bounds__(256, 2) void k_gemm_tc(
    const float* __restrict__ Ab, long Ads, int lda,
    const float* __restrict__ Wb, long Wds, int ldw,
    const float* __restrict__ biasb, int bds,
    float* __restrict__ Cb, long Cds, int ldc,
    int K,
    const float* __restrict__ aux1, float* __restrict__ aux2,
    const float* __restrict__ aux3, float* __restrict__ aux4,
    int tsel0, int tsel1)
{
    __shared__ unsigned As[2][128][20];   // A tile 128x16, pad 20 (conflict-free frags)
    __shared__ unsigned Bs[2][16][136];   // B tile 16x128, pad 136 (conflict-free frags)
    int dir = blockIdx.z;
    const float* A = Ab + dir*Ads;
    const float* W = Wb + dir*Wds;
    const float* bias = biasb + dir*bds;
    float* C = Cb + dir*Cds;
    int bm = blockIdx.y, bn = blockIdx.x;
    int tid = threadIdx.x;
    int wid = tid >> 5, lane = tid & 31;
    int wm = (wid >> 2) * 64;            // warp m offset within CTA tile
    int wn = (wid & 3) * 32;             // warp n offset
    int grp = lane >> 2, quad = lane & 3;

    // gmem staging pointers (each thread: 2 float4 of A, 2 float4 of B per slab)
    const float* Ag = A + (long)(bm*128 + (tid>>2))*lda + (tid&3)*4;
    const float* Bg = W + (long)(tid>>5)*ldw + bn*128 + (tid&31)*4;
    int as_r = tid >> 2, as_c = (tid & 3) * 4;   // As rows: as_r, as_r+64
    int bs_r = tid >> 5, bs_c = (tid & 31) * 4;  // Bs rows: bs_r, bs_r+8

    float acc[4][4][4] = {};
    float4 a0v, a1v, b0v, b1v;

    // prologue: slab 0 -> buf 0
    a0v = *(const float4*)(Ag);
    a1v = *(const float4*)(Ag + (long)64*lda);
    b0v = *(const float4*)(Bg);
    b1v = *(const float4*)(Bg + (long)8*ldw);
    As[0][as_r   ][as_c]=f2tf(a0v.x); As[0][as_r   ][as_c+1]=f2tf(a0v.y); As[0][as_r   ][as_c+2]=f2tf(a0v.z); As[0][as_r   ][as_c+3]=f2tf(a0v.w);
    As[0][as_r+64][as_c]=f2tf(a1v.x); As[0][as_r+64][as_c+1]=f2tf(a1v.y); As[0][as_r+64][as_c+2]=f2tf(a1v.z); As[0][as_r+64][as_c+3]=f2tf(a1v.w);
    Bs[0][bs_r  ][bs_c]=f2tf(b0v.x); Bs[0][bs_r  ][bs_c+1]=f2tf(b0v.y); Bs[0][bs_r  ][bs_c+2]=f2tf(b0v.z); Bs[0][bs_r  ][bs_c+3]=f2tf(b0v.w);
    Bs[0][bs_r+8][bs_c]=f2tf(b1v.x); Bs[0][bs_r+8][bs_c+1]=f2tf(b1v.y); Bs[0][bs_r+8][bs_c+2]=f2tf(b1v.z); Bs[0][bs_r+8][bs_c+3]=f2tf(b1v.w);
    __syncthreads();

    int nslab = K >> 4;
    for (int s = 0; s < nslab; s++){
        int buf = s & 1;
        int k0n = (s+1) << 4;
        bool more = (s+1 < nslab);
        if (more){
            a0v = *(const float4*)(Ag + k0n);
            a1v = *(const float4*)(Ag + (long)64*lda + k0n);
            b0v = *(const float4*)(Bg + (long)k0n*ldw);
            b1v = *(const float4*)(Bg + (long)(k0n+8)*ldw);
        }
        #pragma unroll
        for (int kk = 0; kk < 16; kk += 8){
            unsigned af[4][4];
            #pragma unroll
            for (int mi = 0; mi < 4; mi++){
                int r0 = wm + mi*16 + grp;
                af[mi][0] = As[buf][r0  ][kk+quad];
                af[mi][1] = As[buf][r0+8][kk+quad];
                af[mi][2] = As[buf][r0  ][kk+quad+4];
                af[mi][3] = As[buf][r0+8][kk+quad+4];
            }
            unsigned bf[4][2];
            #pragma unroll
            for (int ni = 0; ni < 4; ni++){
                int c0 = wn + ni*8 + grp;
                bf[ni][0] = Bs[buf][kk+quad  ][c0];
                bf[ni][1] = Bs[buf][kk+quad+4][c0];
            }
            #pragma unroll
            for (int mi = 0; mi < 4; mi++)
                #pragma unroll
                for (int ni = 0; ni < 4; ni++)
                    mma_tf32(acc[mi][ni][0], acc[mi][ni][1], acc[mi][ni][2], acc[mi][ni][3],
                             af[mi][0], af[mi][1], af[mi][2], af[mi][3], bf[ni][0], bf[ni][1]);
        }
        if (more){
            int nb = buf ^ 1;
            As[nb][as_r   ][as_c]=f2tf(a0v.x); As[nb][as_r   ][as_c+1]=f2tf(a0v.y); As[nb][as_r   ][as_c+2]=f2tf(a0v.z); As[nb][as_r   ][as_c+3]=f2tf(a0v.w);
            As[nb][as_r+64][as_c]=f2tf(a1v.x); As[nb][as_r+64][as_c+1]=f2tf(a1v.y); As[nb][as_r+64][as_c+2]=f2tf(a1v.z); As[nb][as_r+64][as_c+3]=f2tf(a1v.w);
            Bs[nb][bs_r  ][bs_c]=f2tf(b0v.x); Bs[nb][bs_r  ][bs_c+1]=f2tf(b0v.y); Bs[nb][bs_r  ][bs_c+2]=f2tf(b0v.z); Bs[nb][bs_r  ][bs_c+3]=f2tf(b0v.w);
            Bs[nb][bs_r+8][bs_c]=f2tf(b1v.x); Bs[nb][bs_r+8][bs_c+1]=f2tf(b1v.y); Bs[nb][bs_r+8][bs_c+2]=f2tf(b1v.z); Bs[nb][bs_r+8][bs_c+3]=f2tf(b1v.w);
        }
        __syncthreads();
    }

    // epilogue: per-element scatter per fragment layout
    #pragma unroll
    for (int mi = 0; mi < 4; mi++){
        #pragma unroll
        for (int ni = 0; ni < 4; ni++){
            int row0 = bm*128 + wm + mi*16 + grp;
            int col0 = bn*128 + wn + ni*8 + quad*2;
            #pragma unroll
            for (int e = 0; e < 4; e++){
                int row = row0 + ((e >> 1) << 3);   // +8 for e=2,3
                int col = col0 + (e & 1);
                float v = acc[mi][ni][e] + bias[col];
                long ro = (long)row*ldc + col;
                if (EPI == 1){
                    if (col < CKQ) v = (v > 0.f) ? v + 1.f : expf(v);
                    C[ro] = v;
                } else if (EPI == 2){
                    float hv = aux1[(long)dir*RD + ro];
                    aux2[(long)dir*RD + ro] = v + hv;              // new h carry
                    int bb = row >> 10, nn = row & 1023;
                    int ts = dir ? tsel1 : tsel0;
                    float xv = aux3[((long)(bb*CL + ts)*CN + nn)*CD + col];
                    C[ro] = v + xv;                                 // x2
                } else if (EPI == 3){
                    C[ro] = v * normcdff(v);
                } else if (EPI == 4){
                    float x2v = aux1[(long)dir*RD + ro];
                    float val = v + x2v;
                    int bb = row >> 10, nn = row & 1023;
                    int ts = dir ? tsel1 : tsel0;
                    long xo = ((long)(bb*CL + ts)*CN + nn)*CD + col;
                    aux4[xo] += val;
                }
            }
        }
    }
}

// ---------------- host ----------------
extern "C" void kernel_launch(void* const* d_in, const int* in_sizes, int n_in,
                              void* d_out, int out_size){
    (void)in_sizes; (void)n_in; (void)out_size;
    const float* x      = (const float*)d_in[0];
    const float* hidden = (const float*)d_in[1];
    const float* spos   = (const float*)d_in[2];
    const float* tpos   = (const float*)d_in[3];
    const float* lni_g  = (const float*)d_in[4];
    const float* lni_b  = (const float*)d_in[5];
    const float* lnh_g  = (const float*)d_in[6];
    const float* lnh_b  = (const float*)d_in[7];
    const float* lno_g  = (const float*)d_in[8];
    const float* lno_b  = (const float*)d_in[9];
    const float* Wqkv   = (const float*)d_in[10];
    const float* bqkv   = (const float*)d_in[11];
    const float* Wqkvh  = (const float*)d_in[12];
    const float* bqkvh  = (const float*)d_in[13];
    const float* Wout   = (const float*)d_in[14];
    const float* bout   = (const float*)d_in[15];
    const float* W1     = (const float*)d_in[16];
    const float* b1     = (const float*)d_in[17];
    const float* W2     = (const float*)d_in[18];
    const float* b2     = (const float*)d_in[19];
    float* out = (float*)d_out;

    float *pWcat, *pbcat, *pA, *pqkv, *po, *px2, *pxn2, *pt1, *phin, *ph, *pxin;
    cudaGetSymbolAddress((void**)&pWcat, g_Wcat);
    cudaGetSymbolAddress((void**)&pbcat, g_bcatv);
    cudaGetSymbolAddress((void**)&pA,    g_Abuf);
    cudaGetSymbolAddress((void**)&pqkv,  g_qkv);
    cudaGetSymbolAddress((void**)&po,    g_obuf);
    cudaGetSymbolAddress((void**)&px2,   g_x2);
    cudaGetSymbolAddress((void**)&pxn2,  g_xn2);
    cudaGetSymbolAddress((void**)&pt1,   g_t1);
    cudaGetSymbolAddress((void**)&phin,  g_hin);
    cudaGetSymbolAddress((void**)&ph,    g_h);
    cudaGetSymbolAddress((void**)&pxin,  g_xin);

    const int eb = 256;
    k_pos  <<<(XTOT+eb-1)/eb, eb>>>(tpos, spos);
    k_stack<<<(2*CNL*CKQ*CN3+eb-1)/eb, eb>>>(Wqkv, Wqkvh);
    k_bcat <<<(2*CNL*CN3+eb-1)/eb, eb>>>(bqkv, bqkvh);

    for (int lay = 0; lay < CNL; lay++){
        // Layer 0 accumulates into d_out (scratch), layer 1 snapshots it via
        // k_addpos into g_xin then re-zeroes d_out and accumulates the final result.
        const float* xsrc = (lay == 0) ? x : out;
        float* yacc       = out;
        k_addpos<<<(XTOT+eb-1)/eb, eb>>>(xsrc);
        cudaMemsetAsync(yacc, 0, (size_t)XTOT*sizeof(float));
        k_copyh<<<(2*RD+eb-1)/eb, eb>>>(hidden);
        for (int t = 0; t < CL; t++){
            int ts0 = t, ts1 = CL-1-t;
            k_buildA<<<dim3(CR,2), 256>>>(t, lay, lni_g, lni_b, lnh_g, lnh_b);
            // QKV: [xn|hn](2048x1536) @ Wcat(1536x2304) + bcat, elu+1 on q,k
            k_gemm_tc<1><<<dim3(CN3/128, CR/128, 2), 256>>>(
                pA, (long)CR*CKQ, CKQ,
                pWcat + (long)lay*CKQ*CN3, (long)CNL*CKQ*CN3, CN3,
                pbcat + lay*CN3, CNL*CN3,
                pqkv, (long)CR*CN3, CN3,
                CKQ,
                nullptr, nullptr, nullptr, nullptr, ts0, ts1);
            k_kv<<<dim3(CH, CB, 2), 256>>>();
            k_o <<<dim3(CN/64, CB*CH, 2), 256>>>();
            // attn proj: o(2048x768) @ Wout + bout; x2 = attn+x_t ; h = attn+hin
            k_gemm_tc<2><<<dim3(CD/128, CR/128, 2), 256>>>(
                po, (long)RD, CD,
                Wout + (long)lay*CD*CD, (long)CNL*CD*CD, CD,
                bout + lay*CD, CNL*CD,
                px2, (long)RD, CD,
                CD,
                phin, ph, pxin, nullptr, ts0, ts1);
            k_ln2<<<dim3(CR,2), 256>>>(lay, lno_g, lno_b);
            // MLP up: xn2(2048x768) @ W1 + b1, gelu
            k_gemm_tc<3><<<dim3(CM/128, CR/128, 2), 256>>>(
                pxn2, (long)RD, CD,
                W1 + (long)lay*CD*CM, (long)CNL*CD*CM, CM,
                b1 + lay*CM, CNL*CM,
                pt1, (long)CR*CM, CM,
                CD,
                nullptr, nullptr, nullptr, nullptr, ts0, ts1);
            // MLP down: t1(2048x3072) @ W2 + b2; yacc[time] += x2 + y
            k_gemm_tc<4><<<dim3(CD/128, CR/128, 2), 256>>>(
                pt1, (long)CR*CM, CM,
                W2 + (long)lay*CM*CD, (long)CNL*CM*CD, CD,
                b2 + lay*CD, CNL*CD,
                px2 /*unused C*/, (long)RD, CD,
                CM,
                px2, nullptr, nullptr, yacc, ts0, ts1);
        }
    }
}